// round 13
// baseline (speedup 1.0000x reference)
#include <cuda_runtime.h>
#include <cuda_bf16.h>
#include <cstdint>

#define B_    16
#define T_    24
#define HH    112
#define WW    112
#define F_    32
#define HP    56
#define NPOS  (HP*HP)       // 3136
#define GPOS  (B_*NPOS)     // 50176
#define D_    (NPOS*F_)     // 100352
#define NKS   20            // k16 steps (288 h + 32 x-pad)
#define NTILES (GPOS/128)   // 392

// combined B fragments: [ks 20][nfg 16][lane 32] x uint4 {bh0,bh1,bl0,bl1}
#define BFRAG_QUADS  (NKS*16*32)      // 10240 uint4
#define BFRAG_BYTES  (BFRAG_QUADS*16) // 163840

// SMEM layout (bytes)
#define SM_BIAS  0
#define SM_MBAR  512
#define SM_BF    1024
#define SM_TOTAL (1024 + BFRAG_BYTES)   // 164864

// ---------------- helpers ----------------
__device__ __forceinline__ uint32_t smem_to_u32(const void* p) {
    uint32_t a;
    asm("{ .reg .u64 t; cvta.to.shared.u64 t, %1; cvt.u32.u64 %0, t; }" : "=r"(a) : "l"(p));
    return a;
}
__device__ __forceinline__ float tanh_fast(float x) {
    float y; asm("tanh.approx.f32 %0, %1;" : "=f"(y) : "f"(x)); return y;
}
#define MBARRIER_INIT(mbar, cnt) \
    asm volatile("mbarrier.init.shared.b64 [%0], %1;" :: "r"((uint32_t)(mbar)), "r"((uint32_t)(cnt)) : "memory")
#define MBARRIER_EXPECT_TX(mbar, tx) \
    asm volatile("mbarrier.arrive.expect_tx.shared.b64 _, [%0], %1;" :: "r"((uint32_t)(mbar)), "r"((uint32_t)(tx)) : "memory")
#define MBARRIER_WAIT_PARITY(mbar, par) do { \
    uint32_t _m = (uint32_t)(mbar); uint32_t _p = (uint32_t)(par); uint32_t _done; \
    asm volatile("{\n\t.reg .pred p;\n\tmbarrier.try_wait.parity.acquire.cta.shared::cta.b64 p, [%1], %2;\n\tselp.b32 %0, 1, 0, p;\n\t}" \
        : "=r"(_done) : "r"(_m), "r"(_p) : "memory"); \
    if (!_done) { \
        asm volatile("{\n\t.reg .pred P1;\n\tWL_%=:\n\tmbarrier.try_wait.parity.acquire.cta.shared::cta.b64 P1, [%0], %1, 0x989680;\n\t@P1 bra.uni WD_%=;\n\tbra.uni WL_%=;\n\tWD_%=:\n\t}" \
            :: "r"(_m), "r"(_p) : "memory"); \
    } \
} while (0)

__device__ __forceinline__ void mma16816(float* c, const uint32_t* a, const uint32_t* b) {
    asm volatile(
        "mma.sync.aligned.m16n8k16.row.col.f32.bf16.bf16.f32 "
        "{%0,%1,%2,%3}, {%4,%5,%6,%7}, {%8,%9}, {%0,%1,%2,%3};"
        : "+f"(c[0]), "+f"(c[1]), "+f"(c[2]), "+f"(c[3])
        : "r"(a[0]), "r"(a[1]), "r"(a[2]), "r"(a[3]), "r"(b[0]), "r"(b[1]));
}

// ---------------- persistent state ----------------
// h-state: interleaved hi/lo, per position 16 feature-pairs: hil[pos*16 + f/2] = {hi(f,f+1), lo(f,f+1)}
__device__ __align__(128) uint2 g_hil[2][(size_t)GPOS * 16];
__device__ __align__(128) float g_c[(size_t)GPOS * F_];
__device__ __align__(128) uint4 g_Bfrag[BFRAG_QUADS];
__device__ __align__(128) float g_bias[128];

// weight for GEMM column ch (original channel = gate*32+feature), row k
__device__ __forceinline__ float wt(int k, int ch, const float* Wk, const float* Uk) {
    if (k < 288) return Uk[(size_t)((k >> 5) * F_ + (k & 31)) * 128 + ch];
    if (k < 315) return Wk[(size_t)(k - 288) * 128 + ch];
    return 0.0f;
}

__global__ void prep_kernel(const float* __restrict__ Wk,
                            const float* __restrict__ Uk,
                            const float* __restrict__ bias) {
    int i0 = blockIdx.x * blockDim.x + threadIdx.x;
    int stride = gridDim.x * blockDim.x;
    for (size_t i = i0; i < (size_t)GPOS * 16; i += stride) {
        g_hil[0][i] = make_uint2(0u, 0u);
    }
    for (size_t i = i0; i < (size_t)GPOS * F_; i += stride) g_c[i] = 0.0f;
    for (int i = i0; i < BFRAG_QUADS; i += stride) {
        int l   = i & 31;         // lane
        int nfg = (i >> 5) & 15;  // global n8-frag
        int ks  = i >> 9;         // k-step
        // column mapping: physical warp-local col -> (feature, gate)
        // nfg = nw4*4 + nf ; col8 = q*2+e (q=tig) ;
        // f = nw4*8 + 2*q + (nf&1) ; g = 2*(nf>>1) + e
        int col8 = l >> 2;
        int q    = col8 >> 1, e = col8 & 1;
        int nw4  = nfg >> 2, nf = nfg & 3;
        int f    = nw4 * 8 + 2 * q + (nf & 1);
        int g    = 2 * (nf >> 1) + e;
        int ch   = g * 32 + f;
        uint32_t bh[2], bl[2];
        #pragma unroll
        for (int j = 0; j < 2; j++) {
            int k0 = ks * 16 + (l & 3) * 2 + j * 8;
            float w0 = wt(k0, ch, Wk, Uk);
            float w1 = wt(k0 + 1, ch, Wk, Uk);
            __nv_bfloat16 h0 = __float2bfloat16(w0);
            __nv_bfloat16 h1 = __float2bfloat16(w1);
            __nv_bfloat16 l0 = __float2bfloat16(w0 - __bfloat162float(h0));
            __nv_bfloat16 l1 = __float2bfloat16(w1 - __bfloat162float(h1));
            bh[j] = (uint32_t)__bfloat16_as_ushort(h0) | ((uint32_t)__bfloat16_as_ushort(h1) << 16);
            bl[j] = (uint32_t)__bfloat16_as_ushort(l0) | ((uint32_t)__bfloat16_as_ushort(l1) << 16);
        }
        g_Bfrag[i] = make_uint4(bh[0], bh[1], bl[0], bl[1]);
    }
    if (i0 < 128) g_bias[i0] = bias[i0];
}

// pack two fp32 into bf16x2 hi and lo parts
__device__ __forceinline__ void pack_hilo(float v0, float v1, uint32_t& hi, uint32_t& lo) {
    __nv_bfloat16 h0 = __float2bfloat16(v0);
    __nv_bfloat16 h1 = __float2bfloat16(v1);
    __nv_bfloat16 l0 = __float2bfloat16(v0 - __bfloat162float(h0));
    __nv_bfloat16 l1 = __float2bfloat16(v1 - __bfloat162float(h1));
    hi = (uint32_t)__bfloat16_as_ushort(h0) | ((uint32_t)__bfloat16_as_ushort(h1) << 16);
    lo = (uint32_t)__bfloat16_as_ushort(l0) | ((uint32_t)__bfloat16_as_ushort(l1) << 16);
}

// A buffer layout per m16 tile mt: buf[mt*8 + 0..3] = Ahi frag, buf[mt*8 + 4..7] = Alo frag
__device__ __forceinline__ void get_off(int tap, const int pr[4], const int pc[4], const int bo[4],
                                        int off[4], bool ok[4]) {
    int dr = tap / 3 - 1, dc = tap % 3 - 1;
    #pragma unroll
    for (int i = 0; i < 4; i++) {
        int hr = pr[i] + dr, hc = pc[i] + dc;
        ok[i]  = ((unsigned)hr < HP) && ((unsigned)hc < HP);
        off[i] = (bo[i] + hr * HP + hc) * 16;   // uint2 index base
    }
}

__device__ __forceinline__ void load_a(uint32_t buf[16],
                                       const uint2* __restrict__ hil,
                                       const int off[4], const bool ok[4], int kh, int tig) {
    const int p0 = kh * 8 + tig;
    #pragma unroll
    for (int mt = 0; mt < 2; mt++) {
        #pragma unroll
        for (int rr = 0; rr < 2; rr++) {
            int i = 2 * mt + rr;
            uint2 v0 = ok[i] ? hil[off[i] + p0]     : make_uint2(0u, 0u);
            uint2 v1 = ok[i] ? hil[off[i] + p0 + 4] : make_uint2(0u, 0u);
            buf[mt*8 + rr]         = v0.x;
            buf[mt*8 + 4 + rr]     = v0.y;
            buf[mt*8 + rr + 2]     = v1.x;
            buf[mt*8 + 4 + rr + 2] = v1.y;
        }
    }
}

__device__ __forceinline__ void do_mmas(float acc[2][4][4], const uint32_t A[16],
                                        const uint4* __restrict__ bF, int ks, int nw4, int lane) {
    #pragma unroll
    for (int nf = 0; nf < 4; nf++) {
        uint4 bv = bF[(ks * 16 + nw4 * 4 + nf) * 32 + lane];
        uint32_t bh[2] = {bv.x, bv.y};
        uint32_t bl[2] = {bv.z, bv.w};
        #pragma unroll
        for (int mt = 0; mt < 2; mt++) {
            mma16816(acc[mt][nf], A + mt * 8, bh);
            mma16816(acc[mt][nf], A + mt * 8, bl);
            mma16816(acc[mt][nf], A + mt * 8 + 4, bh);
        }
    }
}

// ---------------- per-step GEMM kernel ----------------
__global__ void __launch_bounds__(512, 1) step_kernel(
    const float* __restrict__ x, float* __restrict__ out, int t, int parity)
{
    extern __shared__ char smem[];
    float* bias_s = (float*)(smem + SM_BIAS);
    const uint32_t mbar = smem_to_u32(smem) + SM_MBAR;
    const uint4* bF = (const uint4*)(smem + SM_BF);

    const int tid  = threadIdx.x;
    const int wid  = tid >> 5;
    const int lane = tid & 31;
    const int tig  = lane & 3;
    const int rl   = lane >> 2;
    const int m_base = (wid >> 2) * 32;   // 4 m-warps x 32 rows
    const int nw4    = wid & 3;           // 4 n-warps x 4 nfg

    if (tid == 0) MBARRIER_INIT(mbar, 1);
    if (tid < 128) bias_s[tid] = g_bias[tid];
    __syncthreads();
    if (tid == 0) {
        MBARRIER_EXPECT_TX(mbar, BFRAG_BYTES);
        asm volatile("cp.async.bulk.shared::cluster.global.mbarrier::complete_tx::bytes [%0], [%1], %2, [%3];"
                     :: "r"(smem_to_u32(smem) + SM_BF), "l"((const void*)g_Bfrag), "r"(BFRAG_BYTES), "r"(mbar) : "memory");
    }

    // per-thread row info (4 rows: mtile{0,1} x {rl, rl+8})
    int pr[4], pc[4], bo[4];
    #pragma unroll
    for (int i = 0; i < 4; i++) {
        int m  = m_base + rl + ((i >> 1) ? 16 : 0) + ((i & 1) ? 8 : 0);
        int gp = blockIdx.x * 128 + m;
        int b  = gp / NPOS;
        int p  = gp - b * NPOS;
        pr[i] = p / HP;
        pc[i] = p - pr[i] * HP;
        bo[i] = b * NPOS;
    }

    float acc[2][4][4];
    #pragma unroll
    for (int mt = 0; mt < 2; mt++)
        #pragma unroll
        for (int nf = 0; nf < 4; nf++)
            #pragma unroll
            for (int q = 0; q < 4; q++) acc[mt][nf][q] = 0.0f;

    const uint2* hil = g_hil[parity];

    // ---- software-pipelined recurrent taps ----
    int offc[4], offn[4];
    bool okc[4], okn[4];
    uint32_t A0[16], A1[16];

    get_off(0, pr, pc, bo, offc, okc);
    load_a(A0, hil, offc, okc, 0, tig);     // overlaps the B bulk copy

    MBARRIER_WAIT_PARITY(mbar, 0);

    #pragma unroll 1
    for (int tap = 0; tap < 9; tap++) {
        load_a(A1, hil, offc, okc, 1, tig);           // prefetch kh=1
        do_mmas(acc, A0, bF, 2 * tap, nw4, lane);
        if (tap < 8) {
            get_off(tap + 1, pr, pc, bo, offn, okn);
            load_a(A0, hil, offn, okn, 0, tig);       // prefetch next tap kh=0
            #pragma unroll
            for (int i = 0; i < 4; i++) { offc[i] = offn[i]; okc[i] = okn[i]; }
        }
        do_mmas(acc, A1, bF, 2 * tap + 1, nw4, lane);
    }

    // ---- input-conv taps (ks 18,19): x gathered + converted on the fly ----
    #pragma unroll 1
    for (int kh = 0; kh < 2; kh++) {
        const int jb = kh * 16 + tig * 2;
        uint32_t AX[16];
        #pragma unroll
        for (int mt = 0; mt < 2; mt++) {
            #pragma unroll
            for (int rr = 0; rr < 2; rr++) {
                int i = 2 * mt + rr;
                int gp = blockIdx.x * 128 + m_base + rl + mt * 16 + rr * 8;
                int b  = gp / NPOS;
                uint32_t xoff = (uint32_t)(b * T_ + t) * (HH * WW * 3);
                #pragma unroll
                for (int part = 0; part < 2; part++) {
                    float v[2];
                    #pragma unroll
                    for (int e = 0; e < 2; e++) {
                        int j = jb + part * 8 + e;
                        float val = 0.0f;
                        if (j < 27) {
                            int t3 = (j * 11) >> 5;          // j/3
                            int c3 = j - t3 * 3;
                            int kr = (t3 * 11) >> 5;          // t3/3
                            int kc = t3 - kr * 3;
                            int xr = 2 * pr[i] + kr;
                            int xc = 2 * pc[i] + kc;
                            if (xr < HH && xc < WW)
                                val = x[xoff + (uint32_t)xr * (WW * 3) + xc * 3 + c3];
                        }
                        v[e] = val;
                    }
                    pack_hilo(v[0], v[1], AX[mt*8 + rr + 2*part], AX[mt*8 + 4 + rr + 2*part]);
                }
            }
        }
        do_mmas(acc, AX, bF, 18 + kh, nw4, lane);
    }

    // ---- epilogue: gates + state update (register-local, no exchange) ----
    const int f0 = nw4 * 8 + 2 * tig;      // 2 contiguous features
    const int pair = f0 >> 1;              // = nw4*4 + tig
    uint2* hilO = g_hil[parity ^ 1];
    float b0i = bias_s[f0],      b1i = bias_s[f0 + 1];
    float b0f = bias_s[32 + f0], b1f = bias_s[33 + f0];
    float b0c = bias_s[64 + f0], b1c = bias_s[65 + f0];
    float b0o = bias_s[96 + f0], b1o = bias_s[97 + f0];
    #pragma unroll
    for (int mt = 0; mt < 2; mt++) {
        #pragma unroll
        for (int hf = 0; hf < 2; hf++) {
            int m  = m_base + rl + mt * 16 + hf * 8;
            int gp = blockIdx.x * 128 + m;
            int b  = gp / NPOS;
            int p  = gp - b * NPOS;
            float* cb = g_c + (size_t)gp * F_ + f0;
            float2 cold = *(const float2*)cb;
            float cv[2] = {cold.x, cold.y};
            float hv[2];
            #pragma unroll
            for (int ff = 0; ff < 2; ff++) {
                float zi = acc[mt][ff][2 * hf + 0]     + (ff ? b1i : b0i);
                float zf = acc[mt][ff][2 * hf + 1]     + (ff ? b1f : b0f);
                float zc = acc[mt][2 + ff][2 * hf + 0] + (ff ? b1c : b0c);
                float zo = acc[mt][2 + ff][2 * hf + 1] + (ff ? b1o : b0o);
                float iG = __saturatef(fmaf(zi, 0.2f, 0.5f));
                float fG = __saturatef(fmaf(zf, 0.2f, 0.5f));
                float oG = __saturatef(fmaf(zo, 0.2f, 0.5f));
                float cn = fG * cv[ff] + iG * tanh_fast(zc);
                float hn = oG * tanh_fast(cn);
                cv[ff] = cn; hv[ff] = hn;
            }
            uint32_t hi, lo;
            pack_hilo(hv[0], hv[1], hi, lo);
            *(float2*)cb = make_float2(cv[0], cv[1]);
            hilO[(size_t)gp * 16 + pair] = make_uint2(hi, lo);
            float* ob = out + ((size_t)b * T_ + t) * D_ + (size_t)p * F_ + f0;
            *(float2*)ob = make_float2(hv[0], hv[1]);
        }
    }
}

// ---------------- LayerNorm ----------------
__global__ void __launch_bounds__(512) ln_kernel(
    float* __restrict__ y, const float* __restrict__ gamma, const float* __restrict__ beta)
{
    __shared__ float s_sum[16], s_sum2[16], s_stat[2];
    float* row = y + (size_t)blockIdx.x * D_;
    float s = 0.f, s2 = 0.f;
    for (int i = threadIdx.x; i < D_; i += blockDim.x) {
        float v = row[i];
        s += v;
        s2 = fmaf(v, v, s2);
    }
    #pragma unroll
    for (int o = 16; o > 0; o >>= 1) {
        s  += __shfl_xor_sync(0xFFFFFFFFu, s,  o);
        s2 += __shfl_xor_sync(0xFFFFFFFFu, s2, o);
    }
    int w = threadIdx.x >> 5, l = threadIdx.x & 31;
    if (l == 0) { s_sum[w] = s; s_sum2[w] = s2; }
    __syncthreads();
    if (w == 0) {
        s  = (l < 16) ? s_sum[l]  : 0.f;
        s2 = (l < 16) ? s_sum2[l] : 0.f;
        #pragma unroll
        for (int o = 8; o > 0; o >>= 1) {
            s  += __shfl_xor_sync(0xFFFFFFFFu, s,  o);
            s2 += __shfl_xor_sync(0xFFFFFFFFu, s2, o);
        }
        if (l == 0) {
            float mu  = s * (1.0f / D_);
            float var = s2 * (1.0f / D_) - mu * mu;
            s_stat[0] = mu;
            s_stat[1] = rsqrtf(var + 1e-3f);
        }
    }
    __syncthreads();
    float mu = s_stat[0], rs = s_stat[1];
    for (int i = threadIdx.x; i < D_; i += blockDim.x) {
        row[i] = (row[i] - mu) * rs * gamma[i] + beta[i];
    }
}

extern "C" void kernel_launch(void* const* d_in, const int* in_sizes, int n_in,
                              void* d_out, int out_size)
{
    const float* x     = (const float*)d_in[0];
    const float* Wk    = (const float*)d_in[1];
    const float* Uk    = (const float*)d_in[2];
    const float* bias  = (const float*)d_in[3];
    const float* gamma = (const float*)d_in[4];
    const float* beta  = (const float*)d_in[5];
    float* out = (float*)d_out;

    cudaFuncSetAttribute(step_kernel, cudaFuncAttributeMaxDynamicSharedMemorySize, SM_TOTAL);

    prep_kernel<<<512, 256>>>(Wk, Uk, bias);

    for (int t = 0; t < T_; t++) {
        step_kernel<<<NTILES, 512, SM_TOTAL>>>(x, out, t, t & 1);
    }

    ln_kernel<<<B_ * T_, 512>>>(out, gamma, beta);
}